// round 1
// baseline (speedup 1.0000x reference)
#include <cuda_runtime.h>

// ---------------------------------------------------------------------------
// GAT 3-layer forward: CSR build + (GEMM -> el/er -> warp-per-node softmax-agg) x3 + FC
// ---------------------------------------------------------------------------

#define NMAX 50000
#define EMAX 800000

// scratch (static device globals: no allocation allowed in kernel_launch)
__device__ float g_h[NMAX * 100];     // post-GEMM features of current layer
__device__ float g_x[NMAX * 100];     // post-aggregation features (next layer input)
__device__ float g_el[NMAX * 4];
__device__ float g_er[NMAX * 4];
__device__ int   g_cnt[NMAX];
__device__ int   g_ctr[NMAX];
__device__ int   g_off[NMAX + 1];
__device__ int   g_ssrc[EMAX];        // src node ids, grouped by dst

// ---------------------------------------------------------------------------
__global__ void zero_kernel(int* a, int* b, int n) {
    int i = blockIdx.x * blockDim.x + threadIdx.x;
    if (i < n) { a[i] = 0; b[i] = 0; }
}

__global__ void hist_kernel(const int* __restrict__ dst, int* cnt, int e) {
    int i = blockIdx.x * blockDim.x + threadIdx.x;
    if (i < e) atomicAdd(&cnt[dst[i]], 1);
}

// single-block chunked exclusive scan (n ~ 50k, trivial runtime)
__global__ void scan_kernel(const int* __restrict__ cnt, int* off, int n) {
    __shared__ int sh[1024];
    __shared__ int carry_sh;
    int tid = threadIdx.x;
    if (tid == 0) carry_sh = 0;
    __syncthreads();
    for (int base = 0; base < n; base += 1024) {
        int i = base + tid;
        int v = (i < n) ? cnt[i] : 0;
        sh[tid] = v;
        __syncthreads();
        for (int o = 1; o < 1024; o <<= 1) {
            int t = (tid >= o) ? sh[tid - o] : 0;
            __syncthreads();
            sh[tid] += t;
            __syncthreads();
        }
        int carry = carry_sh;
        if (i < n) off[i] = carry + sh[tid] - v;   // exclusive
        __syncthreads();
        if (tid == 0) carry_sh = carry + sh[1023];
        __syncthreads();
    }
    if (tid == 0) off[n] = carry_sh;
}

__global__ void scatter_kernel(const int* __restrict__ src, const int* __restrict__ dst,
                               const int* __restrict__ off, int* ctr, int* ssrc, int e) {
    int i = blockIdx.x * blockDim.x + threadIdx.x;
    if (i < e) {
        int d = dst[i];
        int p = off[d] + atomicAdd(&ctr[d], 1);
        ssrc[p] = src[i];
    }
}

// ---------------------------------------------------------------------------
// h = x @ W   (x: [n,K], W: [K,M] row-major). W staged in static shared.
// block: 32x8 threads, each warp handles 8 nodes; lane covers m = lane + 32*c.
template <int K, int M, int MC>
__global__ void gemm_kernel(const float* __restrict__ x, const float* __restrict__ W,
                            float* __restrict__ out, int n) {
    __shared__ float Wsh[K * M];
    int tid = threadIdx.y * 32 + threadIdx.x;
    for (int idx = tid; idx < K * M; idx += 256) Wsh[idx] = W[idx];
    __syncthreads();

    const int NT = 8;
    int lane = threadIdx.x;
    int base = blockIdx.x * 64 + threadIdx.y * NT;

    float acc[NT][MC];
#pragma unroll
    for (int i = 0; i < NT; i++)
#pragma unroll
        for (int c = 0; c < MC; c++) acc[i][c] = 0.f;

    for (int k = 0; k < K; k++) {
        float w[MC];
#pragma unroll
        for (int c = 0; c < MC; c++) {
            int m = lane + 32 * c;
            w[c] = (m < M) ? Wsh[k * M + m] : 0.f;
        }
#pragma unroll
        for (int i = 0; i < NT; i++) {
            int nn = base + i;
            if (nn < n) {
                float xv = __ldg(&x[nn * K + k]);
#pragma unroll
                for (int c = 0; c < MC; c++) acc[i][c] += xv * w[c];
            }
        }
    }
#pragma unroll
    for (int i = 0; i < NT; i++) {
        int nn = base + i;
        if (nn < n) {
#pragma unroll
            for (int c = 0; c < MC; c++) {
                int m = lane + 32 * c;
                if (m < M) out[nn * M + m] = acc[i][c];
            }
        }
    }
}

// ---------------------------------------------------------------------------
// el[n,h] = sum_d h[n,h*25+d]*al[h,d];  er likewise. One thread per (n,h).
template <int H>
__global__ void elr_kernel(const float* __restrict__ hbuf,
                           const float* __restrict__ al, const float* __restrict__ ar,
                           float* __restrict__ el, float* __restrict__ er, int n) {
    int t = blockIdx.x * blockDim.x + threadIdx.x;
    if (t >= n * H) return;
    int node = t / H, h = t % H;
    const float* hr = hbuf + node * (H * 25) + h * 25;
    float sl = 0.f, sr = 0.f;
#pragma unroll
    for (int d = 0; d < 25; d++) {
        float v = hr[d];
        sl += v * al[h * 25 + d];
        sr += v * ar[h * 25 + d];
    }
    el[t] = sl;
    er[t] = sr;
}

// ---------------------------------------------------------------------------
// Warp-per-destination-node edge softmax + aggregation.
// out[n,f] = (sum_j exp(e_j - m_h) * h[src_j, f]) / max(sum_j exp(e_j - m_h), 1e-9) + b[f]
// with e_j = leaky_relu(el[src_j,h] + er[n,h], 0.2), h = f / 25.
template <int H, int MC>
__global__ void agg_kernel(const float* __restrict__ hbuf,
                           const float* __restrict__ el, const float* __restrict__ er,
                           const int* __restrict__ off, const int* __restrict__ ssrc,
                           const float* __restrict__ bias, float* __restrict__ out, int n) {
    const int HD = H * 25;
    int lane = threadIdx.x & 31;
    int w = (blockIdx.x * blockDim.x + threadIdx.x) >> 5;
    if (w >= n) return;

    int start = off[w], end = off[w + 1];

    float er_n[H];
#pragma unroll
    for (int h = 0; h < H; h++) er_n[h] = er[w * H + h];
    float er_l = (lane < H) ? er_n[0] : 0.f;
#pragma unroll
    for (int h = 1; h < H; h++) if (lane == h) er_l = er_n[h];

    // pass 1: per-head max over incoming edges (lane-strided, shfl reduce)
    float m[H];
#pragma unroll
    for (int h = 0; h < H; h++) m[h] = -3.0e38f;
    for (int j = start + lane; j < end; j += 32) {
        int s = ssrc[j];
#pragma unroll
        for (int h = 0; h < H; h++) {
            float e = el[s * H + h] + er_n[h];
            e = (e > 0.f) ? e : 0.2f * e;
            m[h] = fmaxf(m[h], e);
        }
    }
#pragma unroll
    for (int o = 16; o > 0; o >>= 1)
#pragma unroll
        for (int h = 0; h < H; h++)
            m[h] = fmaxf(m[h], __shfl_xor_sync(0xffffffffu, m[h], o));

    float m_l = m[0];
#pragma unroll
    for (int h = 1; h < H; h++) if (lane == h) m_l = m[h];

    // lane's feature columns f = lane + 32*c map to head hk[c]
    int hk[MC];
#pragma unroll
    for (int c = 0; c < MC; c++) {
        int f = lane + 32 * c;
        hk[c] = (f < HD) ? f / 25 : 0;
    }

    float acc[MC];
#pragma unroll
    for (int c = 0; c < MC; c++) acc[c] = 0.f;
    float sum_l = 0.f;

    // pass 2: whole warp walks edges together; lanes<H compute exp, broadcast
    for (int j = start; j < end; j++) {
        int s = ssrc[j];                       // broadcast load
        float ex_l = 0.f;
        if (lane < H) {
            float e = el[s * H + lane] + er_l;
            e = (e > 0.f) ? e : 0.2f * e;
            ex_l = __expf(e - m_l);
            sum_l += ex_l;
        }
#pragma unroll
        for (int c = 0; c < MC; c++) {
            float exv = __shfl_sync(0xffffffffu, ex_l, hk[c]);
            int f = lane + 32 * c;
            if (f < HD) acc[c] += exv * hbuf[s * HD + f];
        }
    }

#pragma unroll
    for (int c = 0; c < MC; c++) {
        float sh = __shfl_sync(0xffffffffu, sum_l, hk[c]);
        int f = lane + 32 * c;
        if (f < HD) out[w * HD + f] = acc[c] / fmaxf(sh, 1e-9f) + bias[f];
    }
}

// ---------------------------------------------------------------------------
__global__ void fc_kernel(const float* __restrict__ h, const float* __restrict__ fw,
                          const float* __restrict__ fb, float* __restrict__ out, int n) {
    int i = blockIdx.x * blockDim.x + threadIdx.x;
    if (i >= n) return;
    float z = fb[0];
#pragma unroll
    for (int d = 0; d < 25; d++) z += h[i * 25 + d] * fw[d];
    out[i] = 1.f / (1.f + __expf(-z));
}

// ---------------------------------------------------------------------------
extern "C" void kernel_launch(void* const* d_in, const int* in_sizes, int n_in,
                              void* d_out, int out_size) {
    const float* feat = (const float*)d_in[0];
    const int*   src  = (const int*)d_in[1];
    const int*   dst  = (const int*)d_in[2];
    const float* W1   = (const float*)d_in[3];
    const float* al1  = (const float*)d_in[4];
    const float* ar1  = (const float*)d_in[5];
    const float* b1   = (const float*)d_in[6];
    const float* W2   = (const float*)d_in[7];
    const float* al2  = (const float*)d_in[8];
    const float* ar2  = (const float*)d_in[9];
    const float* b2   = (const float*)d_in[10];
    const float* W3   = (const float*)d_in[11];
    const float* al3  = (const float*)d_in[12];
    const float* ar3  = (const float*)d_in[13];
    const float* b3   = (const float*)d_in[14];
    const float* fcw  = (const float*)d_in[15];
    const float* fcb  = (const float*)d_in[16];
    float* out = (float*)d_out;

    int N = in_sizes[0] / 93;
    int E = in_sizes[1];

    float *hbuf, *xbuf, *el, *er;
    int *cnt, *ctr, *off, *ssrc;
    cudaGetSymbolAddress((void**)&hbuf, g_h);
    cudaGetSymbolAddress((void**)&xbuf, g_x);
    cudaGetSymbolAddress((void**)&el, g_el);
    cudaGetSymbolAddress((void**)&er, g_er);
    cudaGetSymbolAddress((void**)&cnt, g_cnt);
    cudaGetSymbolAddress((void**)&ctr, g_ctr);
    cudaGetSymbolAddress((void**)&off, g_off);
    cudaGetSymbolAddress((void**)&ssrc, g_ssrc);

    // --- CSR build (per-launch, deterministic work) ---
    zero_kernel<<<(N + 255) / 256, 256>>>(cnt, ctr, N);
    hist_kernel<<<(E + 255) / 256, 256>>>(dst, cnt, E);
    scan_kernel<<<1, 1024>>>(cnt, off, N);
    scatter_kernel<<<(E + 255) / 256, 256>>>(src, dst, off, ctr, ssrc, E);

    dim3 gblk(32, 8);
    int ggrid = (N + 63) / 64;

    // --- layer 1: 93 -> 4 heads x 25 = 100 ---
    gemm_kernel<93, 100, 4><<<ggrid, gblk>>>(feat, W1, hbuf, N);
    elr_kernel<4><<<(N * 4 + 255) / 256, 256>>>(hbuf, al1, ar1, el, er, N);
    agg_kernel<4, 4><<<(N + 7) / 8, 256>>>(hbuf, el, er, off, ssrc, b1, xbuf, N);

    // --- layer 2: 100 -> 2 x 25 = 50 ---
    gemm_kernel<100, 50, 2><<<ggrid, gblk>>>(xbuf, W2, hbuf, N);
    elr_kernel<2><<<(N * 2 + 255) / 256, 256>>>(hbuf, al2, ar2, el, er, N);
    agg_kernel<2, 2><<<(N + 7) / 8, 256>>>(hbuf, el, er, off, ssrc, b2, xbuf, N);

    // --- layer 3: 50 -> 1 x 25 = 25 ---
    gemm_kernel<50, 25, 1><<<ggrid, gblk>>>(xbuf, W3, hbuf, N);
    elr_kernel<1><<<(N + 255) / 256, 256>>>(hbuf, al3, ar3, el, er, N);
    agg_kernel<1, 1><<<(N + 7) / 8, 256>>>(hbuf, el, er, off, ssrc, b3, xbuf, N);

    // --- FC + sigmoid ---
    fc_kernel<<<(N + 255) / 256, 256>>>(xbuf, fcw, fcb, out, N);
}

// round 2
// speedup vs baseline: 1.1732x; 1.1732x over previous
#include <cuda_runtime.h>

// ---------------------------------------------------------------------------
// GAT 3-layer forward. CSR build (parallel scan) + per layer:
//   gemm -> elr -> agg (edge-weight precompute + sums, then gather-aggregate)
// Softmax max-shift dropped (algebraically identical, values O(1)).
// FC+sigmoid fused into layer-3 agg epilogue.
// ---------------------------------------------------------------------------

#define NMAX 50000
#define EMAX 800000
#define NBMAX 64   // ceil(NMAX/1024) = 49

__device__ float g_h[NMAX * 100];      // post-GEMM features
__device__ float g_x[NMAX * 100];      // post-aggregation features
__device__ float g_el[NMAX * 4];
__device__ float g_er[NMAX * 4];
__device__ float g_ew[EMAX * 4];       // per-edge softmax numerators
__device__ int   g_cnt[NMAX];
__device__ int   g_ctr[NMAX];
__device__ int   g_loc[NMAX];          // chunk-local exclusive prefix
__device__ int   g_bsum[NBMAX];        // per-chunk totals -> exclusive base
__device__ int   g_ssrc[EMAX];         // src ids grouped by dst

// ---------------------------------------------------------------------------
__global__ void zero_kernel(int* a, int n) {
    int i = blockIdx.x * blockDim.x + threadIdx.x;
    if (i < n) a[i] = 0;
}

__global__ void hist_kernel(const int* __restrict__ dst, int* cnt, int e) {
    int i = blockIdx.x * blockDim.x + threadIdx.x;
    if (i < e) atomicAdd(&cnt[dst[i]], 1);
}

// per-chunk (1024) exclusive scan; also zero ctr
__global__ void scan1_kernel(const int* __restrict__ cnt, int* loc, int* bsum,
                             int* ctr, int n) {
    __shared__ int sh[1024];
    int tid = threadIdx.x;
    int i = blockIdx.x * 1024 + tid;
    int v = (i < n) ? cnt[i] : 0;
    if (i < n) ctr[i] = 0;
    sh[tid] = v;
    __syncthreads();
    for (int o = 1; o < 1024; o <<= 1) {
        int t = (tid >= o) ? sh[tid - o] : 0;
        __syncthreads();
        sh[tid] += t;
        __syncthreads();
    }
    if (i < n) loc[i] = sh[tid] - v;
    if (tid == 1023) bsum[blockIdx.x] = sh[1023];
}

// exclusive scan of <=64 chunk totals, in place
__global__ void scan2_kernel(int* bsum, int nb) {
    __shared__ int sh[64];
    int tid = threadIdx.x;
    int v = (tid < nb) ? bsum[tid] : 0;
    sh[tid] = v;
    __syncthreads();
    for (int o = 1; o < 64; o <<= 1) {
        int t = (tid >= o) ? sh[tid - o] : 0;
        __syncthreads();
        sh[tid] += t;
        __syncthreads();
    }
    if (tid < nb) bsum[tid] = sh[tid] - v;
}

__global__ void scatter_kernel(const int* __restrict__ src, const int* __restrict__ dst,
                               const int* __restrict__ loc, const int* __restrict__ bsum,
                               int* ctr, int* ssrc, int e) {
    int i = blockIdx.x * blockDim.x + threadIdx.x;
    if (i < e) {
        int d = dst[i];
        int p = loc[d] + bsum[d >> 10] + atomicAdd(&ctr[d], 1);
        ssrc[p] = src[i];
    }
}

// ---------------------------------------------------------------------------
// h = x @ W. W staged in shared; warp handles 8 nodes, lane covers m=lane+32c.
template <int K, int M, int MC>
__global__ void gemm_kernel(const float* __restrict__ x, const float* __restrict__ W,
                            float* __restrict__ out, int n) {
    __shared__ float Wsh[K * M];
    int tid = threadIdx.y * 32 + threadIdx.x;
    for (int idx = tid; idx < K * M; idx += 256) Wsh[idx] = W[idx];
    __syncthreads();

    const int NT = 8;
    int lane = threadIdx.x;
    int base = blockIdx.x * 64 + threadIdx.y * NT;

    float acc[NT][MC];
#pragma unroll
    for (int i = 0; i < NT; i++)
#pragma unroll
        for (int c = 0; c < MC; c++) acc[i][c] = 0.f;

    for (int k = 0; k < K; k++) {
        float w[MC];
#pragma unroll
        for (int c = 0; c < MC; c++) {
            int m = lane + 32 * c;
            w[c] = (m < M) ? Wsh[k * M + m] : 0.f;
        }
#pragma unroll
        for (int i = 0; i < NT; i++) {
            int nn = base + i;
            if (nn < n) {
                float xv = __ldg(&x[nn * K + k]);
#pragma unroll
                for (int c = 0; c < MC; c++) acc[i][c] += xv * w[c];
            }
        }
    }
#pragma unroll
    for (int i = 0; i < NT; i++) {
        int nn = base + i;
        if (nn < n) {
#pragma unroll
            for (int c = 0; c < MC; c++) {
                int m = lane + 32 * c;
                if (m < M) out[nn * M + m] = acc[i][c];
            }
        }
    }
}

// ---------------------------------------------------------------------------
template <int H>
__global__ void elr_kernel(const float* __restrict__ hbuf,
                           const float* __restrict__ al, const float* __restrict__ ar,
                           float* __restrict__ el, float* __restrict__ er, int n) {
    int t = blockIdx.x * blockDim.x + threadIdx.x;
    if (t >= n * H) return;
    int node = t / H, h = t % H;
    const float* hr = hbuf + node * (H * 25) + h * 25;
    float sl = 0.f, sr = 0.f;
#pragma unroll
    for (int d = 0; d < 25; d++) {
        float v = hr[d];
        sl += v * al[h * 25 + d];
        sr += v * ar[h * 25 + d];
    }
    el[t] = sl;
    er[t] = sr;
}

// ---------------------------------------------------------------------------
template <int H>
__device__ __forceinline__ float pick(const float* a, int idx) {
    float r = a[0];
#pragma unroll
    for (int h = 1; h < H; h++) if (idx == h) r = a[h];
    return r;
}

// Warp-per-destination-node softmax + aggregation (no max-shift).
// Pass1 (lane-strided): ew = exp(leaky(el[s]+er[n])), accumulate per-head sums.
// Pass2 (edge-serial, lane=feature): acc += ew * h[src]; normalize + bias.
template <int H, int MC, bool FC>
__global__ void agg_kernel(const float* __restrict__ hbuf,
                           const float* __restrict__ el, const float* __restrict__ er,
                           const int* __restrict__ loc, const int* __restrict__ bsum,
                           const int* __restrict__ ssrc,
                           const float* __restrict__ bias,
                           float* __restrict__ ew,
                           float* __restrict__ out,
                           const float* __restrict__ fcw, const float* __restrict__ fcb,
                           int n, int e) {
    const int HD = H * 25;
    int lane = threadIdx.x & 31;
    int w = (blockIdx.x * blockDim.x + threadIdx.x) >> 5;
    if (w >= n) return;

    int start = loc[w] + bsum[w >> 10];
    int end = (w + 1 < n) ? loc[w + 1] + bsum[(w + 1) >> 10] : e;

    float er_n[H];
#pragma unroll
    for (int h = 0; h < H; h++) er_n[h] = er[w * H + h];

    float sum[H];
#pragma unroll
    for (int h = 0; h < H; h++) sum[h] = 0.f;

    for (int j = start + lane; j < end; j += 32) {
        int s = ssrc[j];
        float ev[H];
        if constexpr (H == 4) {
            float4 t = *(const float4*)(el + s * 4);
            ev[0] = t.x; ev[1] = t.y; ev[2] = t.z; ev[3] = t.w;
        } else if constexpr (H == 2) {
            float2 t = *(const float2*)(el + s * 2);
            ev[0] = t.x; ev[1] = t.y;
        } else {
            ev[0] = el[s];
        }
        float ex[H];
#pragma unroll
        for (int h = 0; h < H; h++) {
            float q = ev[h] + er_n[h];
            q = (q > 0.f) ? q : 0.2f * q;
            float xv = __expf(q);
            ex[h] = xv;
            sum[h] += xv;
        }
        if constexpr (H == 4) {
            *(float4*)(ew + j * 4) = make_float4(ex[0], ex[1], ex[2], ex[3]);
        } else if constexpr (H == 2) {
            *(float2*)(ew + j * 2) = make_float2(ex[0], ex[1]);
        } else {
            ew[j] = ex[0];
        }
    }
#pragma unroll
    for (int o = 16; o > 0; o >>= 1)
#pragma unroll
        for (int h = 0; h < H; h++)
            sum[h] += __shfl_xor_sync(0xffffffffu, sum[h], o);
    __syncwarp();

    int fidx[MC], hk[MC];
    bool act[MC];
#pragma unroll
    for (int c = 0; c < MC; c++) {
        int f = lane + 32 * c;
        fidx[c] = f;
        act[c] = (f < HD);
        hk[c] = act[c] ? f / 25 : 0;
    }

    float acc[MC];
#pragma unroll
    for (int c = 0; c < MC; c++) acc[c] = 0.f;

#pragma unroll 2
    for (int j = start; j < end; j++) {
        int s = ssrc[j];
        const float* hr = hbuf + (long)s * HD;
#pragma unroll
        for (int c = 0; c < MC; c++) {
            if (act[c]) {
                float exv = ew[j * H + hk[c]];
                acc[c] += exv * hr[fidx[c]];
            }
        }
    }

    if constexpr (FC) {
        // H==1, MC==1: fused fc + sigmoid
        float v = 0.f;
        if (act[0]) v = acc[0] / fmaxf(sum[0], 1e-9f) + bias[fidx[0]];
        float z = (lane < 25) ? v * fcw[lane] : 0.f;
#pragma unroll
        for (int o = 16; o > 0; o >>= 1) z += __shfl_xor_sync(0xffffffffu, z, o);
        if (lane == 0) out[w] = 1.f / (1.f + __expf(-(z + fcb[0])));
    } else {
#pragma unroll
        for (int c = 0; c < MC; c++)
            if (act[c])
                out[w * HD + fidx[c]] =
                    acc[c] / fmaxf(pick<H>(sum, hk[c]), 1e-9f) + bias[fidx[c]];
    }
}

// ---------------------------------------------------------------------------
extern "C" void kernel_launch(void* const* d_in, const int* in_sizes, int n_in,
                              void* d_out, int out_size) {
    const float* feat = (const float*)d_in[0];
    const int*   src  = (const int*)d_in[1];
    const int*   dst  = (const int*)d_in[2];
    const float* W1   = (const float*)d_in[3];
    const float* al1  = (const float*)d_in[4];
    const float* ar1  = (const float*)d_in[5];
    const float* b1   = (const float*)d_in[6];
    const float* W2   = (const float*)d_in[7];
    const float* al2  = (const float*)d_in[8];
    const float* ar2  = (const float*)d_in[9];
    const float* b2   = (const float*)d_in[10];
    const float* W3   = (const float*)d_in[11];
    const float* al3  = (const float*)d_in[12];
    const float* ar3  = (const float*)d_in[13];
    const float* b3   = (const float*)d_in[14];
    const float* fcw  = (const float*)d_in[15];
    const float* fcb  = (const float*)d_in[16];
    float* out = (float*)d_out;

    int N = in_sizes[0] / 93;
    int E = in_sizes[1];
    int NB = (N + 1023) / 1024;

    float *hbuf, *xbuf, *el, *er, *ew;
    int *cnt, *ctr, *loc, *bsum, *ssrc;
    cudaGetSymbolAddress((void**)&hbuf, g_h);
    cudaGetSymbolAddress((void**)&xbuf, g_x);
    cudaGetSymbolAddress((void**)&el, g_el);
    cudaGetSymbolAddress((void**)&er, g_er);
    cudaGetSymbolAddress((void**)&ew, g_ew);
    cudaGetSymbolAddress((void**)&cnt, g_cnt);
    cudaGetSymbolAddress((void**)&ctr, g_ctr);
    cudaGetSymbolAddress((void**)&loc, g_loc);
    cudaGetSymbolAddress((void**)&bsum, g_bsum);
    cudaGetSymbolAddress((void**)&ssrc, g_ssrc);

    // --- CSR build ---
    zero_kernel<<<(N + 255) / 256, 256>>>(cnt, N);
    hist_kernel<<<(E + 255) / 256, 256>>>(dst, cnt, E);
    scan1_kernel<<<NB, 1024>>>(cnt, loc, bsum, ctr, N);
    scan2_kernel<<<1, 64>>>(bsum, NB);
    scatter_kernel<<<(E + 255) / 256, 256>>>(src, dst, loc, bsum, ctr, ssrc, E);

    dim3 gblk(32, 8);
    int ggrid = (N + 63) / 64;
    int agrid = (N + 7) / 8;

    // --- layer 1: 93 -> 4x25 ---
    gemm_kernel<93, 100, 4><<<ggrid, gblk>>>(feat, W1, hbuf, N);
    elr_kernel<4><<<(N * 4 + 255) / 256, 256>>>(hbuf, al1, ar1, el, er, N);
    agg_kernel<4, 4, false><<<agrid, 256>>>(hbuf, el, er, loc, bsum, ssrc, b1,
                                            ew, xbuf, fcw, fcb, N, E);

    // --- layer 2: 100 -> 2x25 ---
    gemm_kernel<100, 50, 2><<<ggrid, gblk>>>(xbuf, W2, hbuf, N);
    elr_kernel<2><<<(N * 2 + 255) / 256, 256>>>(hbuf, al2, ar2, el, er, N);
    agg_kernel<2, 2, false><<<agrid, 256>>>(hbuf, el, er, loc, bsum, ssrc, b2,
                                            ew, xbuf, fcw, fcb, N, E);

    // --- layer 3: 50 -> 1x25, fc+sigmoid fused ---
    gemm_kernel<50, 25, 1><<<ggrid, gblk>>>(xbuf, W3, hbuf, N);
    elr_kernel<1><<<(N + 255) / 256, 256>>>(hbuf, al3, ar3, el, er, N);
    agg_kernel<1, 1, true><<<agrid, 256>>>(hbuf, el, er, loc, bsum, ssrc, b3,
                                           ew, out, fcw, fcb, N, E);
}